// round 4
// baseline (speedup 1.0000x reference)
#include <cuda_runtime.h>
#include <cstdint>

// ---------------- problem constants ----------------
#define NBATCH   32
#define C_DIM    256
#define PIX      4096                   // 64*64 pixels per image
#define KCL      128                    // clusters
#define OUT_BINS 129
#define TILE_P   128                    // pixels per CTA
#define NTH      256                    // 8 warps
#define KC       32                     // channels per chunk
#define NCHUNK   8                      // 256/32
#define A_PITCH  136                    // As[ch][px] pitch (conflict-free frags)
#define B_PITCH  36                     // Bs[cl][ch] pitch (conflict-free frags)
#define DELTA    0.75f                  // tf32 error slack for exact-rescue

__device__ float g_c2[KCL];

// ---------------- helpers ----------------
__device__ __forceinline__ uint32_t tf32_rna(float x) {
    uint32_t u;
    asm("cvt.rna.tf32.f32 %0, %1;" : "=r"(u) : "f"(x));
    return u;
}
__device__ __forceinline__ void mma_tf32(float& d0, float& d1, float& d2, float& d3,
                                         uint32_t a0, uint32_t a1, uint32_t a2, uint32_t a3,
                                         uint32_t b0, uint32_t b1) {
    asm volatile(
        "mma.sync.aligned.m16n8k8.row.col.f32.tf32.tf32.f32 "
        "{%0,%1,%2,%3}, {%4,%5,%6,%7}, {%8,%9}, {%0,%1,%2,%3};"
        : "+f"(d0), "+f"(d1), "+f"(d2), "+f"(d3)
        : "r"(a0), "r"(a1), "r"(a2), "r"(a3), "r"(b0), "r"(b1));
}
// order-preserving float -> u32 key (ascending)
__device__ __forceinline__ uint32_t fkey(float f) {
    uint32_t u = __float_as_uint(f);
    return u ^ ((u & 0x80000000u) ? 0xFFFFFFFFu : 0x80000000u);
}

// ---------------- c2 kernel ----------------
__global__ void c2_kernel(const float* __restrict__ centers) {
    int k = threadIdx.x;
    if (k >= KCL) return;
    const float* row = centers + (size_t)k * C_DIM;
    float s = 0.f;
#pragma unroll 8
    for (int c = 0; c < C_DIM; ++c) s = fmaf(row[c], row[c], s);
    g_c2[k] = s;
}

// ---------------- main kernel ----------------
// dot[p][k] via tf32 mma.sync; dist = c2[k] - 2*dot; exact fp32 rescue for
// all clusters within DELTA of the tf32 min; histogram via atomics.
__global__ __launch_bounds__(NTH, 2)
void vq_mma_kernel(const float* __restrict__ x,
                   const float* __restrict__ centers,
                   float* __restrict__ out) {
    __shared__ float As[KC][A_PITCH];       // x chunk (tf32 bits), [channel][pixel]
    __shared__ float Bs[KCL][B_PITCH];      // centers chunk (tf32 bits), [cluster][channel]

    const int tid  = threadIdx.x;
    const int wid  = tid >> 5;
    const int lane = tid & 31;
    const int g    = lane >> 2;             // fragment group 0..7
    const int t    = lane & 3;              // thread-in-group 0..3

    const int warp_m = wid & 3;             // pixel quarter (32 px)
    const int warp_n = wid >> 2;            // cluster half (64 cl)
    const int pm = warp_m * 32;
    const int cn = warp_n * 64;

    const int ct = blockIdx.x;              // 1024 tiles
    const int n  = ct >> 5;
    const int p0 = (ct & 31) * TILE_P;
    const float* xn = x + (size_t)n * C_DIM * PIX + p0;

    float acc[2][8][4];
#pragma unroll
    for (int mt = 0; mt < 2; ++mt)
#pragma unroll
        for (int nt = 0; nt < 8; ++nt)
#pragma unroll
            for (int c = 0; c < 4; ++c) acc[mt][nt][c] = 0.f;

    // staging indices (per chunk, per thread: 4 float4 from x, 4 from centers)
    const int a_ch = tid >> 3;              // 0..31
    const int a_px = (tid & 7) * 16;        // 0..112 step 16
    const int b_cl = tid >> 1;              // 0..127
    const int b_ch = (tid & 1) * 16;        // 0 or 16

    for (int ch0 = 0; ch0 < C_DIM; ch0 += KC) {
        __syncthreads();                    // previous chunk's MMAs done
        // ---- stage: LDG (batched) -> cvt.rna.tf32 -> STS ----
        float4 av[4], bv[4];
#pragma unroll
        for (int v = 0; v < 4; ++v)
            av[v] = *reinterpret_cast<const float4*>(
                xn + (size_t)(ch0 + a_ch) * PIX + a_px + v * 4);
#pragma unroll
        for (int v = 0; v < 4; ++v)
            bv[v] = *reinterpret_cast<const float4*>(
                centers + (size_t)b_cl * C_DIM + ch0 + b_ch + v * 4);
#pragma unroll
        for (int v = 0; v < 4; ++v) {
            uint32_t* d = reinterpret_cast<uint32_t*>(&As[a_ch][a_px + v * 4]);
            d[0] = tf32_rna(av[v].x); d[1] = tf32_rna(av[v].y);
            d[2] = tf32_rna(av[v].z); d[3] = tf32_rna(av[v].w);
        }
#pragma unroll
        for (int v = 0; v < 4; ++v) {
            uint32_t* d = reinterpret_cast<uint32_t*>(&Bs[b_cl][b_ch + v * 4]);
            d[0] = tf32_rna(bv[v].x); d[1] = tf32_rna(bv[v].y);
            d[2] = tf32_rna(bv[v].z); d[3] = tf32_rna(bv[v].w);
        }
        __syncthreads();

        // ---- compute: 4 k8-slices ----
#pragma unroll
        for (int ks = 0; ks < 4; ++ks) {
            const int kb = ks * 8;
            uint32_t a[2][4];
#pragma unroll
            for (int mt = 0; mt < 2; ++mt) {
                int r = pm + mt * 16 + g;
                a[mt][0] = __float_as_uint(As[kb + t][r]);
                a[mt][1] = __float_as_uint(As[kb + t][r + 8]);
                a[mt][2] = __float_as_uint(As[kb + t + 4][r]);
                a[mt][3] = __float_as_uint(As[kb + t + 4][r + 8]);
            }
            uint32_t b[8][2];
#pragma unroll
            for (int nt = 0; nt < 8; ++nt) {
                int cl = cn + nt * 8 + g;
                b[nt][0] = __float_as_uint(Bs[cl][kb + t]);
                b[nt][1] = __float_as_uint(Bs[cl][kb + t + 4]);
            }
#pragma unroll
            for (int mt = 0; mt < 2; ++mt)
#pragma unroll
                for (int nt = 0; nt < 8; ++nt)
                    mma_tf32(acc[mt][nt][0], acc[mt][nt][1], acc[mt][nt][2], acc[mt][nt][3],
                             a[mt][0], a[mt][1], a[mt][2], a[mt][3],
                             b[nt][0], b[nt][1]);
        }
    }
    __syncthreads();                        // smem free for epilogue reuse

    // ---- epilogue smem (reuse As/Bs storage) ----
    float* halfMin = &As[0][0];                                     // [2][128]
    float* gmin    = halfMin + 256;                                 // [128]
    unsigned long long* minkey =
        reinterpret_cast<unsigned long long*>(&As[8][0]);           // [128], 8B aligned

    // c2 for this thread's 16 clusters
    float c2v[8][2];
#pragma unroll
    for (int nt = 0; nt < 8; ++nt) {
        c2v[nt][0] = g_c2[cn + nt * 8 + t * 2];
        c2v[nt][1] = g_c2[cn + nt * 8 + t * 2 + 1];
    }

    // pass 1: tf32 min per pixel-row (value only)
#pragma unroll
    for (int mt = 0; mt < 2; ++mt)
#pragma unroll
        for (int rh = 0; rh < 2; ++rh) {
            float m = 3.4e38f;
#pragma unroll
            for (int nt = 0; nt < 8; ++nt) {
                m = fminf(m, fmaf(-2.f, acc[mt][nt][rh * 2], c2v[nt][0]));
                m = fminf(m, fmaf(-2.f, acc[mt][nt][rh * 2 + 1], c2v[nt][1]));
            }
            m = fminf(m, __shfl_xor_sync(0xffffffffu, m, 1));
            m = fminf(m, __shfl_xor_sync(0xffffffffu, m, 2));
            if (t == 0) halfMin[warp_n * 128 + pm + mt * 16 + rh * 8 + g] = m;
        }
    __syncthreads();
    if (tid < TILE_P) {
        gmin[tid]   = fminf(halfMin[tid], halfMin[128 + tid]);
        minkey[tid] = ~0ull;
    }
    __syncthreads();

    // pass 2: exact fp32 rescue for candidates within DELTA of tf32 min
#pragma unroll
    for (int mt = 0; mt < 2; ++mt)
#pragma unroll
        for (int rh = 0; rh < 2; ++rh) {
            const int px  = pm + mt * 16 + rh * 8 + g;
            const float thr = gmin[px] + DELTA;
#pragma unroll
            for (int nt = 0; nt < 8; ++nt)
#pragma unroll
                for (int c = 0; c < 2; ++c) {
                    float d = fmaf(-2.f, acc[mt][nt][rh * 2 + c], c2v[nt][c]);
                    if (d <= thr) {
                        const int k = cn + nt * 8 + t * 2 + c;
                        const float* xc = xn + px;
                        const float* cr = centers + (size_t)k * C_DIM;
                        float s = 0.f;
#pragma unroll 8
                        for (int cc = 0; cc < C_DIM; ++cc)
                            s = fmaf(__ldg(xc + (size_t)cc * PIX), __ldg(cr + cc), s);
                        float e = fmaf(-2.f, s, g_c2[k]);
                        unsigned long long key =
                            ((unsigned long long)fkey(e) << 32) | (unsigned)k;
                        atomicMin(&minkey[px], key);
                    }
                }
        }
    __syncthreads();

    // histogram
    if (tid < TILE_P) {
        int bi = (int)(unsigned)(minkey[tid] & 0xFFFFFFFFull);
        int pg = p0 + tid;
        int h = pg >> 6, w = pg & 63;
        int sblk = (h >> 3) * 8 + (w >> 3);
        atomicAdd(&out[((size_t)n * 64 + sblk) * OUT_BINS + bi + 1], 1.0f / 64.0f);
    }
}

// ---------------- launch ----------------
extern "C" void kernel_launch(void* const* d_in, const int* in_sizes, int n_in,
                              void* d_out, int out_size) {
    const float* x       = (const float*)d_in[0];
    const float* centers = (const float*)d_in[1];
    float* out           = (float*)d_out;

    cudaMemsetAsync(d_out, 0, (size_t)out_size * sizeof(float), 0);
    c2_kernel<<<1, KCL>>>(centers);

    int nblocks = (NBATCH * PIX) / TILE_P;   // 1024
    vq_mma_kernel<<<nblocks, NTH>>>(x, centers, out);
}

// round 5
// speedup vs baseline: 4.1736x; 4.1736x over previous
#include <cuda_runtime.h>
#include <cstdint>

// ---------------- problem constants ----------------
#define NBATCH   32
#define C_DIM    256
#define PIX      4096                   // 64*64 pixels per image
#define KCL      128
#define OUT_BINS 129
#define TILE_P   128                    // pixels per CTA
#define NTH      256                    // 8 warps
#define KC       32                     // channels per chunk
#define NCHUNK   8
#define A_PITCH  136                    // As[ch][px] pitch in floats (136%32==8 -> conflict-free frags)
#define B_PITCH  36                     // Bs[cl][ch] pitch in floats (36%32==4  -> conflict-free frags)
#define AS_WORDS (KC * A_PITCH)         // 4352
#define BS_WORDS (KCL * B_PITCH)        // 4608
#define STAGE_WORDS (AS_WORDS + BS_WORDS)   // 8960 floats = 35840 B
#define NSTAGE   3
#define DELTA    1.0f
#define LIST_CAP 2048

__device__ float g_c2[KCL];

// ---------------- helpers ----------------
__device__ __forceinline__ uint32_t smem_u32(const void* p) {
    uint32_t a;
    asm("{ .reg .u64 t; cvta.to.shared.u64 t, %1; cvt.u32.u64 %0, t; }" : "=r"(a) : "l"(p));
    return a;
}
__device__ __forceinline__ uint32_t tf32_rna(float x) {
    uint32_t u;
    asm("cvt.rna.tf32.f32 %0, %1;" : "=r"(u) : "f"(x));
    return u;
}
__device__ __forceinline__ void cpasync16(uint32_t dst, const void* src) {
    asm volatile("cp.async.ca.shared.global [%0], [%1], 16;" :: "r"(dst), "l"(src));
}
__device__ __forceinline__ void mma_tf32(float& d0, float& d1, float& d2, float& d3,
                                         uint32_t a0, uint32_t a1, uint32_t a2, uint32_t a3,
                                         uint32_t b0, uint32_t b1) {
    asm volatile(
        "mma.sync.aligned.m16n8k8.row.col.f32.tf32.tf32.f32 "
        "{%0,%1,%2,%3}, {%4,%5,%6,%7}, {%8,%9}, {%0,%1,%2,%3};"
        : "+f"(d0), "+f"(d1), "+f"(d2), "+f"(d3)
        : "r"(a0), "r"(a1), "r"(a2), "r"(a3), "r"(b0), "r"(b1));
}
__device__ __forceinline__ uint32_t fkey(float f) {       // order-preserving float->u32
    uint32_t u = __float_as_uint(f);
    return u ^ ((u & 0x80000000u) ? 0xFFFFFFFFu : 0x80000000u);
}
__device__ __forceinline__ float unfkey(uint32_t k) {
    uint32_t u = (k & 0x80000000u) ? (k ^ 0x80000000u) : ~k;
    return __uint_as_float(u);
}

// ---------------- c2 kernel ----------------
__global__ void c2_kernel(const float* __restrict__ centers) {
    int k = threadIdx.x;
    if (k >= KCL) return;
    const float* row = centers + (size_t)k * C_DIM;
    float s = 0.f;
#pragma unroll 8
    for (int c = 0; c < C_DIM; ++c) s = fmaf(row[c], row[c], s);
    g_c2[k] = s;
}

// ---------------- main kernel ----------------
__global__ __launch_bounds__(NTH, 2)
void vq_mma_kernel(const float* __restrict__ x,
                   const float* __restrict__ centers,
                   float* __restrict__ out) {
    extern __shared__ float smem[];
    const uint32_t smem_b = smem_u32(smem);

    const int tid  = threadIdx.x;
    const int wid  = tid >> 5;
    const int lane = tid & 31;
    const int g    = lane >> 2;            // 0..7
    const int t    = lane & 3;             // 0..3

    const int pm = (wid & 3) * 32;         // pixel quarter
    const int cn = (wid >> 2) * 64;        // cluster half

    const int ct = blockIdx.x;
    const int n  = ct >> 5;
    const int p0 = (ct & 31) * TILE_P;
    const float* xn = x + (size_t)n * C_DIM * PIX + p0;

    float acc[2][8][4];
#pragma unroll
    for (int mt = 0; mt < 2; ++mt)
#pragma unroll
        for (int nt = 0; nt < 8; ++nt)
#pragma unroll
            for (int c = 0; c < 4; ++c) acc[mt][nt][c] = 0.f;

    // ---- cp.async stage issue: chunk ch0 into stage s ----
    auto issue = [&](int chunk, int s) {
        const int ch0 = chunk * KC;
        const uint32_t sA = smem_b + (uint32_t)s * STAGE_WORDS * 4u;
        const uint32_t sB = sA + AS_WORDS * 4u;
#pragma unroll
        for (int i = 0; i < 4; ++i) {       // x: 32ch x 128px = 1024 segs of 16B
            int idx = tid + NTH * i;
            int ch  = idx >> 5;
            int sg  = idx & 31;
            cpasync16(sA + (uint32_t)(ch * A_PITCH + sg * 4) * 4u,
                      xn + (size_t)(ch0 + ch) * PIX + sg * 4);
        }
#pragma unroll
        for (int i = 0; i < 4; ++i) {       // centers: 128cl x 32ch = 1024 segs
            int idx = tid + NTH * i;
            int cl  = idx >> 3;
            int sg  = idx & 7;
            cpasync16(sB + (uint32_t)(cl * B_PITCH + sg * 4) * 4u,
                      centers + (size_t)cl * C_DIM + ch0 + sg * 4);
        }
        asm volatile("cp.async.commit_group;" ::: "memory");
    };

    issue(0, 0); issue(1, 1); issue(2, 2);

    for (int c = 0; c < NCHUNK; ++c) {
        if (c <= 5)      asm volatile("cp.async.wait_group 2;" ::: "memory");
        else if (c == 6) asm volatile("cp.async.wait_group 1;" ::: "memory");
        else             asm volatile("cp.async.wait_group 0;" ::: "memory");
        __syncthreads();

        const float* sA = smem + (size_t)(c % NSTAGE) * STAGE_WORDS;
        const float* sB = sA + AS_WORDS;

#pragma unroll
        for (int ks = 0; ks < 4; ++ks) {
            const int kb = ks * 8;
            uint32_t a[2][4];
#pragma unroll
            for (int mt = 0; mt < 2; ++mt) {
                int r = pm + mt * 16 + g;
                a[mt][0] = tf32_rna(sA[(kb + t)     * A_PITCH + r]);
                a[mt][1] = tf32_rna(sA[(kb + t)     * A_PITCH + r + 8]);
                a[mt][2] = tf32_rna(sA[(kb + t + 4) * A_PITCH + r]);
                a[mt][3] = tf32_rna(sA[(kb + t + 4) * A_PITCH + r + 8]);
            }
            uint32_t b[8][2];
#pragma unroll
            for (int nt = 0; nt < 8; ++nt) {
                int cl = cn + nt * 8 + g;
                b[nt][0] = tf32_rna(sB[cl * B_PITCH + kb + t]);
                b[nt][1] = tf32_rna(sB[cl * B_PITCH + kb + t + 4]);
            }
#pragma unroll
            for (int mt = 0; mt < 2; ++mt)
#pragma unroll
                for (int nt = 0; nt < 8; ++nt)
                    mma_tf32(acc[mt][nt][0], acc[mt][nt][1], acc[mt][nt][2], acc[mt][nt][3],
                             a[mt][0], a[mt][1], a[mt][2], a[mt][3],
                             b[nt][0], b[nt][1]);
        }
        __syncthreads();
        if (c + 3 < NCHUNK) issue(c + 3, c % NSTAGE);
    }

    // ---------------- epilogue ----------------
    // smem overlay (stage 0 region, all compute reads done)
    unsigned long long* tf32key  = reinterpret_cast<unsigned long long*>(smem);        // [128]
    unsigned long long* exactkey = tf32key + 128;                                      // [128]
    unsigned int*       cnt      = reinterpret_cast<unsigned int*>(exactkey + 128);    // [128]
    unsigned int*       list     = cnt + 128;                                          // [LIST_CAP]
    unsigned int*       listn    = list + LIST_CAP;

    __syncthreads();
    if (tid < TILE_P) {
        tf32key[tid]  = ~0ull;
        exactkey[tid] = ~0ull;
        cnt[tid]      = 0u;
    }
    if (tid == 0) *listn = 0u;
    __syncthreads();

    float c2v[8][2];
#pragma unroll
    for (int nt = 0; nt < 8; ++nt) {
        c2v[nt][0] = g_c2[cn + nt * 8 + t * 2];
        c2v[nt][1] = g_c2[cn + nt * 8 + t * 2 + 1];
    }

    // ---- phase A: tf32 argmin per pixel (packed key, lowest-k ties) ----
#pragma unroll
    for (int mt = 0; mt < 2; ++mt)
#pragma unroll
        for (int rh = 0; rh < 2; ++rh) {
            const int px = pm + mt * 16 + rh * 8 + g;
            float bv = 3.4e38f; int bk = -1;
#pragma unroll
            for (int nt = 0; nt < 8; ++nt)
#pragma unroll
                for (int cc = 0; cc < 2; ++cc) {
                    float d = fmaf(-2.f, acc[mt][nt][rh * 2 + cc], c2v[nt][cc]);
                    if (d < bv) { bv = d; bk = cn + nt * 8 + t * 2 + cc; }
                }
            unsigned long long key = ((unsigned long long)fkey(bv) << 32) | (unsigned)bk;
            unsigned long long o = __shfl_xor_sync(0xffffffffu, key, 1);
            if (o < key) key = o;
            o = __shfl_xor_sync(0xffffffffu, key, 2);
            if (o < key) key = o;
            if (t == 0) atomicMin(&tf32key[px], key);
        }
    __syncthreads();

    // ---- phase B: count/push candidates within DELTA of tf32 min ----
#pragma unroll
    for (int mt = 0; mt < 2; ++mt)
#pragma unroll
        for (int rh = 0; rh < 2; ++rh) {
            const int px = pm + mt * 16 + rh * 8 + g;
            const float thr = unfkey((uint32_t)(tf32key[px] >> 32)) + DELTA;
            int cnt_loc = 0;
#pragma unroll
            for (int nt = 0; nt < 8; ++nt)
#pragma unroll
                for (int cc = 0; cc < 2; ++cc) {
                    float d = fmaf(-2.f, acc[mt][nt][rh * 2 + cc], c2v[nt][cc]);
                    if (d <= thr) {
                        ++cnt_loc;
                        unsigned e = ((unsigned)px << 8) | (unsigned)(cn + nt * 8 + t * 2 + cc);
                        unsigned il = atomicAdd(listn, 1u);
                        if (il < LIST_CAP) list[il] = e;
                    }
                }
            if (cnt_loc) atomicAdd(&cnt[px], (unsigned)cnt_loc);
        }
    __syncthreads();

    // ---- phase C: warp-cooperative exact rescue for ambiguous pixels ----
    const int nl = (int)min(*listn, (unsigned)LIST_CAP);
    for (int i = wid; i < nl; i += 8) {
        unsigned e = list[i];
        int px = e >> 8, k = e & 255;
        if (cnt[px] < 2u) continue;
        const float* cr = centers + (size_t)k * C_DIM;
        float s = 0.f;
#pragma unroll
        for (int j = 0; j < 8; ++j) {
            int cc = lane * 8 + j;
            s = fmaf(__ldg(xn + (size_t)cc * PIX + px), __ldg(cr + cc), s);
        }
#pragma unroll
        for (int o = 16; o >= 1; o >>= 1) s += __shfl_xor_sync(0xffffffffu, s, o);
        if (lane == 0) {
            float ed = fmaf(-2.f, s, g_c2[k]);
            atomicMin(&exactkey[px],
                      ((unsigned long long)fkey(ed) << 32) | (unsigned)k);
        }
    }
    __syncthreads();

    // ---- histogram ----
    if (tid < TILE_P) {
        unsigned long long key = (cnt[tid] >= 2u) ? exactkey[tid] : tf32key[tid];
        int bi = (int)(unsigned)(key & 0xFFFFFFFFull);
        int pg = p0 + tid;
        int h = pg >> 6, w = pg & 63;
        int sblk = (h >> 3) * 8 + (w >> 3);
        atomicAdd(&out[((size_t)n * 64 + sblk) * OUT_BINS + bi + 1], 1.0f / 64.0f);
    }
}

// ---------------- launch ----------------
#define SMEM_BYTES (NSTAGE * STAGE_WORDS * 4)    // 107520

extern "C" void kernel_launch(void* const* d_in, const int* in_sizes, int n_in,
                              void* d_out, int out_size) {
    const float* x       = (const float*)d_in[0];
    const float* centers = (const float*)d_in[1];
    float* out           = (float*)d_out;

    cudaFuncSetAttribute(vq_mma_kernel, cudaFuncAttributeMaxDynamicSharedMemorySize, SMEM_BYTES);

    cudaMemsetAsync(d_out, 0, (size_t)out_size * sizeof(float), 0);
    c2_kernel<<<1, KCL>>>(centers);

    int nblocks = (NBATCH * PIX) / TILE_P;   // 1024
    vq_mma_kernel<<<nblocks, NTH, SMEM_BYTES>>>(x, centers, out);
}

// round 6
// speedup vs baseline: 4.6377x; 1.1112x over previous
#include <cuda_runtime.h>
#include <cstdint>

// ---------------- problem constants ----------------
#define NBATCH   32
#define C_DIM    256
#define PIX      4096
#define KCL      128
#define OUT_BINS 129
#define TILE_P   128
#define NTH      256                    // 8 warps
#define KC       32
#define NCHUNK   8
#define A_PITCH  136                    // conflict-free a-frags
#define B_PITCH  36                     // conflict-free b-frags
#define AS_WORDS (KC * A_PITCH)         // 4352
#define BS_WORDS (KCL * B_PITCH)        // 4608
#define STAGE_WORDS (AS_WORDS + BS_WORDS)
#define NSTAGE   3
#define DELTA    1.0f
#define LIST_CAP 2048

__device__ float g_c2[KCL];

// ---------------- helpers ----------------
__device__ __forceinline__ uint32_t smem_u32(const void* p) {
    uint32_t a;
    asm("{ .reg .u64 t; cvta.to.shared.u64 t, %1; cvt.u32.u64 %0, t; }" : "=r"(a) : "l"(p));
    return a;
}
__device__ __forceinline__ uint32_t tf32_rna(float x) {
    uint32_t u;
    asm("cvt.rna.tf32.f32 %0, %1;" : "=r"(u) : "f"(x));
    return u;
}
__device__ __forceinline__ void cpasync16(uint32_t dst, const void* src) {
    asm volatile("cp.async.ca.shared.global [%0], [%1], 16;" :: "r"(dst), "l"(src));
}
__device__ __forceinline__ void mma_tf32(float& d0, float& d1, float& d2, float& d3,
                                         uint32_t a0, uint32_t a1, uint32_t a2, uint32_t a3,
                                         uint32_t b0, uint32_t b1) {
    asm volatile(
        "mma.sync.aligned.m16n8k8.row.col.f32.tf32.tf32.f32 "
        "{%0,%1,%2,%3}, {%4,%5,%6,%7}, {%8,%9}, {%0,%1,%2,%3};"
        : "+f"(d0), "+f"(d1), "+f"(d2), "+f"(d3)
        : "r"(a0), "r"(a1), "r"(a2), "r"(a3), "r"(b0), "r"(b1));
}
__device__ __forceinline__ uint32_t fkey(float f) {
    uint32_t u = __float_as_uint(f);
    return u ^ ((u & 0x80000000u) ? 0xFFFFFFFFu : 0x80000000u);
}
__device__ __forceinline__ float unfkey(uint32_t k) {
    uint32_t u = (k & 0x80000000u) ? (k ^ 0x80000000u) : ~k;
    return __uint_as_float(u);
}

// ---------------- c2 kernel: one warp per cluster ----------------
__global__ void c2_kernel(const float* __restrict__ centers) {
    int warp = (blockIdx.x * blockDim.x + threadIdx.x) >> 5;   // 0..127
    int lane = threadIdx.x & 31;
    if (warp >= KCL) return;
    const float* row = centers + (size_t)warp * C_DIM;
    float s = 0.f;
#pragma unroll
    for (int j = 0; j < 8; ++j) {
        float v = row[lane * 8 + j];
        s = fmaf(v, v, s);
    }
#pragma unroll
    for (int o = 16; o >= 1; o >>= 1) s += __shfl_xor_sync(0xffffffffu, s, o);
    if (lane == 0) g_c2[warp] = s;
}

// ---------------- main kernel ----------------
__global__ __launch_bounds__(NTH, 2)
void vq_mma_kernel(const float* __restrict__ x,
                   const float* __restrict__ centers,
                   float* __restrict__ out) {
    extern __shared__ float smem[];
    const uint32_t smem_b = smem_u32(smem);

    const int tid  = threadIdx.x;
    const int wid  = tid >> 5;
    const int lane = tid & 31;
    const int g    = lane >> 2;
    const int t    = lane & 3;

    const int pm = (wid & 3) * 32;
    const int cn = (wid >> 2) * 64;

    const int ct = blockIdx.x;
    const int n  = ct >> 5;
    const int p0 = (ct & 31) * TILE_P;
    const float* xn = x + (size_t)n * C_DIM * PIX + p0;

    float acc[2][8][4];
#pragma unroll
    for (int mt = 0; mt < 2; ++mt)
#pragma unroll
        for (int nt = 0; nt < 8; ++nt)
#pragma unroll
            for (int c = 0; c < 4; ++c) acc[mt][nt][c] = 0.f;

    auto issue = [&](int chunk, int s) {
        const int ch0 = chunk * KC;
        const uint32_t sAa = smem_b + (uint32_t)s * STAGE_WORDS * 4u;
        const uint32_t sBa = sAa + AS_WORDS * 4u;
#pragma unroll
        for (int i = 0; i < 4; ++i) {
            int idx = tid + NTH * i;
            int ch  = idx >> 5;
            int sg  = idx & 31;
            cpasync16(sAa + (uint32_t)(ch * A_PITCH + sg * 4) * 4u,
                      xn + (size_t)(ch0 + ch) * PIX + sg * 4);
        }
#pragma unroll
        for (int i = 0; i < 4; ++i) {
            int idx = tid + NTH * i;
            int cl  = idx >> 3;
            int sg  = idx & 7;
            cpasync16(sBa + (uint32_t)(cl * B_PITCH + sg * 4) * 4u,
                      centers + (size_t)cl * C_DIM + ch0 + sg * 4);
        }
        asm volatile("cp.async.commit_group;" ::: "memory");
    };

    issue(0, 0); issue(1, 1); issue(2, 2);

    for (int c = 0; c < NCHUNK; ++c) {
        if (c <= 5)      asm volatile("cp.async.wait_group 2;" ::: "memory");
        else if (c == 6) asm volatile("cp.async.wait_group 1;" ::: "memory");
        else             asm volatile("cp.async.wait_group 0;" ::: "memory");
        __syncthreads();

        const float* sA = smem + (size_t)(c % NSTAGE) * STAGE_WORDS;
        const float* sB = sA + AS_WORDS;

        uint32_t ac[2][4], bc[8][2], an[2][4], bn[8][2];

#define LOAD_FRAGS(A_, B_, kb)                                             \
        do {                                                               \
            _Pragma("unroll")                                              \
            for (int mt = 0; mt < 2; ++mt) {                               \
                int r = pm + mt * 16 + g;                                  \
                A_[mt][0] = tf32_rna(sA[(kb + t)     * A_PITCH + r]);      \
                A_[mt][1] = tf32_rna(sA[(kb + t)     * A_PITCH + r + 8]);  \
                A_[mt][2] = tf32_rna(sA[(kb + t + 4) * A_PITCH + r]);      \
                A_[mt][3] = tf32_rna(sA[(kb + t + 4) * A_PITCH + r + 8]);  \
            }                                                              \
            _Pragma("unroll")                                              \
            for (int nt = 0; nt < 8; ++nt) {                               \
                int cl = cn + nt * 8 + g;                                  \
                B_[nt][0] = tf32_rna(sB[cl * B_PITCH + kb + t]);           \
                B_[nt][1] = tf32_rna(sB[cl * B_PITCH + kb + t + 4]);       \
            }                                                              \
        } while (0)

#define DO_MMAS(A_, B_)                                                    \
        do {                                                               \
            _Pragma("unroll")                                              \
            for (int mt = 0; mt < 2; ++mt)                                 \
                _Pragma("unroll")                                          \
                for (int nt = 0; nt < 8; ++nt)                             \
                    mma_tf32(acc[mt][nt][0], acc[mt][nt][1],               \
                             acc[mt][nt][2], acc[mt][nt][3],               \
                             A_[mt][0], A_[mt][1], A_[mt][2], A_[mt][3],   \
                             B_[nt][0], B_[nt][1]);                        \
        } while (0)

        // software-pipelined k-slices: prefetch ks+1 frags during MMAs of ks
        LOAD_FRAGS(ac, bc, 0);
        LOAD_FRAGS(an, bn, 8);
        DO_MMAS(ac, bc);
        LOAD_FRAGS(ac, bc, 16);
        DO_MMAS(an, bn);
        LOAD_FRAGS(an, bn, 24);
        DO_MMAS(ac, bc);
        // all smem reads for this stage are done -> release buffer early,
        // overlap final MMA batch with next cp.async issue
        __syncthreads();
        if (c + 3 < NCHUNK) issue(c + 3, c % NSTAGE);
        DO_MMAS(an, bn);
    }

    // ---------------- epilogue ----------------
    unsigned long long* tf32key  = reinterpret_cast<unsigned long long*>(smem);       // [128]
    unsigned long long* exactkey = tf32key + 128;                                     // [128]
    unsigned int*       cnt      = reinterpret_cast<unsigned int*>(exactkey + 128);   // [128]
    unsigned int*       list     = cnt + 128;                                         // [LIST_CAP]
    unsigned int*       listn    = list + LIST_CAP;

    __syncthreads();
    if (tid < TILE_P) {
        tf32key[tid]  = ~0ull;
        exactkey[tid] = ~0ull;
        cnt[tid]      = 0u;
    }
    if (tid == 0) *listn = 0u;
    __syncthreads();

    float c2v[8][2];
#pragma unroll
    for (int nt = 0; nt < 8; ++nt) {
        c2v[nt][0] = g_c2[cn + nt * 8 + t * 2];
        c2v[nt][1] = g_c2[cn + nt * 8 + t * 2 + 1];
    }

    // ---- phase A: tf32 argmin per pixel ----
#pragma unroll
    for (int mt = 0; mt < 2; ++mt)
#pragma unroll
        for (int rh = 0; rh < 2; ++rh) {
            const int px = pm + mt * 16 + rh * 8 + g;
            float bv = 3.4e38f; int bk = -1;
#pragma unroll
            for (int nt = 0; nt < 8; ++nt)
#pragma unroll
                for (int cc = 0; cc < 2; ++cc) {
                    float d = fmaf(-2.f, acc[mt][nt][rh * 2 + cc], c2v[nt][cc]);
                    if (d < bv) { bv = d; bk = cn + nt * 8 + t * 2 + cc; }
                }
            unsigned long long key = ((unsigned long long)fkey(bv) << 32) | (unsigned)bk;
            unsigned long long o = __shfl_xor_sync(0xffffffffu, key, 1);
            if (o < key) key = o;
            o = __shfl_xor_sync(0xffffffffu, key, 2);
            if (o < key) key = o;
            if (t == 0) atomicMin(&tf32key[px], key);
        }
    __syncthreads();

    // ---- phase B1: count candidates per pixel (spread-address atomics) ----
#pragma unroll
    for (int mt = 0; mt < 2; ++mt)
#pragma unroll
        for (int rh = 0; rh < 2; ++rh) {
            const int px = pm + mt * 16 + rh * 8 + g;
            const float thr = unfkey((uint32_t)(tf32key[px] >> 32)) + DELTA;
            int cl = 0;
#pragma unroll
            for (int nt = 0; nt < 8; ++nt)
#pragma unroll
                for (int cc = 0; cc < 2; ++cc)
                    if (fmaf(-2.f, acc[mt][nt][rh * 2 + cc], c2v[nt][cc]) <= thr) ++cl;
            if (cl) atomicAdd(&cnt[px], (unsigned)cl);
        }
    __syncthreads();

    // ---- phase B2: push only ambiguous pixels' candidates ----
#pragma unroll
    for (int mt = 0; mt < 2; ++mt)
#pragma unroll
        for (int rh = 0; rh < 2; ++rh) {
            const int px = pm + mt * 16 + rh * 8 + g;
            if (cnt[px] < 2u) continue;
            const float thr = unfkey((uint32_t)(tf32key[px] >> 32)) + DELTA;
#pragma unroll
            for (int nt = 0; nt < 8; ++nt)
#pragma unroll
                for (int cc = 0; cc < 2; ++cc)
                    if (fmaf(-2.f, acc[mt][nt][rh * 2 + cc], c2v[nt][cc]) <= thr) {
                        unsigned e = ((unsigned)px << 8) |
                                     (unsigned)(cn + nt * 8 + t * 2 + cc);
                        unsigned il = atomicAdd(listn, 1u);
                        if (il < LIST_CAP) list[il] = e;
                    }
        }
    __syncthreads();

    // ---- phase C: warp-cooperative exact rescue ----
    const int nl = (int)min(*listn, (unsigned)LIST_CAP);
    for (int i = wid; i < nl; i += 8) {
        unsigned e = list[i];
        int px = e >> 8, k = e & 255;
        const float* cr = centers + (size_t)k * C_DIM;
        float s = 0.f;
#pragma unroll
        for (int j = 0; j < 8; ++j) {
            int cc = lane * 8 + j;
            s = fmaf(__ldg(xn + (size_t)cc * PIX + px), __ldg(cr + cc), s);
        }
#pragma unroll
        for (int o = 16; o >= 1; o >>= 1) s += __shfl_xor_sync(0xffffffffu, s, o);
        if (lane == 0) {
            float ed = fmaf(-2.f, s, g_c2[k]);
            atomicMin(&exactkey[px],
                      ((unsigned long long)fkey(ed) << 32) | (unsigned)k);
        }
    }
    __syncthreads();

    // ---- histogram ----
    if (tid < TILE_P) {
        unsigned long long key = (cnt[tid] >= 2u) ? exactkey[tid] : tf32key[tid];
        int bi = (int)(unsigned)(key & 0xFFFFFFFFull);
        int pg = p0 + tid;
        int h = pg >> 6, w = pg & 63;
        int sblk = (h >> 3) * 8 + (w >> 3);
        atomicAdd(&out[((size_t)n * 64 + sblk) * OUT_BINS + bi + 1], 1.0f / 64.0f);
    }
}

// ---------------- launch ----------------
#define SMEM_BYTES (NSTAGE * STAGE_WORDS * 4)

extern "C" void kernel_launch(void* const* d_in, const int* in_sizes, int n_in,
                              void* d_out, int out_size) {
    const float* x       = (const float*)d_in[0];
    const float* centers = (const float*)d_in[1];
    float* out           = (float*)d_out;

    cudaFuncSetAttribute(vq_mma_kernel, cudaFuncAttributeMaxDynamicSharedMemorySize, SMEM_BYTES);

    cudaMemsetAsync(d_out, 0, (size_t)out_size * sizeof(float), 0);
    c2_kernel<<<(KCL * 32 + 255) / 256, 256>>>(centers);

    int nblocks = (NBATCH * PIX) / TILE_P;   // 1024
    vq_mma_kernel<<<nblocks, NTH, SMEM_BYTES>>>(x, centers, out);
}